// round 2
// baseline (speedup 1.0000x reference)
#include <cuda_runtime.h>
#include <math.h>

// Problem constants
#define BATCH 8
#define CH    512
#define HW    4096
#define GROUPS 32
#define CPG   16        // channels per group
#define EPS   1e-5f
#define SCALE 0.04419417382415922f   // 512^-0.5

// ---------------------------------------------------------------------------
// Scratch (device globals; allocation in kernel_launch is forbidden)
// g_t is reused for the attention output (tokens dead after V projection).
// ---------------------------------------------------------------------------
__device__ float g_t [(long long)BATCH * HW * CH];   // tokens, later attn out
__device__ float g_q [(long long)BATCH * HW * CH];   // (B,HW,C)
__device__ float g_k [(long long)BATCH * HW * CH];   // (B,HW,C)
__device__ float g_vt[(long long)BATCH * CH * HW];   // V transposed (B,C,HW)
__device__ float g_s [(long long)BATCH * HW * HW];   // scores (B,HW,HW) ~537MB

// ---------------------------------------------------------------------------
// Reductions
// ---------------------------------------------------------------------------
__device__ __forceinline__ float warpSum(float v) {
#pragma unroll
    for (int o = 16; o > 0; o >>= 1) v += __shfl_xor_sync(0xffffffffu, v, o);
    return v;
}
__device__ __forceinline__ float warpMax(float v) {
#pragma unroll
    for (int o = 16; o > 0; o >>= 1) v = fmaxf(v, __shfl_xor_sync(0xffffffffu, v, o));
    return v;
}

// ---------------------------------------------------------------------------
// GroupNorm + transpose to token-major (B,HW,C)
// one block per (b, group): reduce 16 ch x 4096 px, then normalize + affine,
// staging through smem so both global read and global write are coalesced.
// ---------------------------------------------------------------------------
__global__ void __launch_bounds__(256) groupnorm_kernel(
    const float* __restrict__ x, const float* __restrict__ gamma,
    const float* __restrict__ beta, float* __restrict__ t)
{
    const int bg = blockIdx.x;
    const int b = bg >> 5, g = bg & 31;
    const int tid = threadIdx.x;
    const float* xg = x + ((long long)b * CH + (long long)g * CPG) * HW;

    // ---- pass 1: sum / sumsq over 16*4096 = 65536 floats ----
    float s = 0.f, ss = 0.f;
    const float4* x4 = (const float4*)xg;
    const int n4 = CPG * HW / 4;  // 16384
    for (int i = tid; i < n4; i += 256) {
        float4 v = x4[i];
        s  += v.x + v.y + v.z + v.w;
        ss += v.x*v.x + v.y*v.y + v.z*v.z + v.w*v.w;
    }
    s = warpSum(s); ss = warpSum(ss);
    __shared__ float shs[8], shss[8];
    __shared__ float s_mean, s_rstd;
    const int lane = tid & 31, wid = tid >> 5;
    if (lane == 0) { shs[wid] = s; shss[wid] = ss; }
    __syncthreads();
    if (tid < 32) {
        float a = (lane < 8) ? shs[lane]  : 0.f;
        float c = (lane < 8) ? shss[lane] : 0.f;
        a = warpSum(a); c = warpSum(c);
        if (lane == 0) {
            const float inv_n = 1.f / (float)(CPG * HW);
            float mean = a * inv_n;
            float var  = c * inv_n - mean * mean;
            s_mean = mean;
            s_rstd = rsqrtf(var + EPS);
        }
    }
    __syncthreads();
    const float mean = s_mean, rstd = s_rstd;

    // ---- pass 2: normalize + transpose write ----
    const int cl = tid & 15;       // channel within group (write phase)
    const int pr = tid >> 4;       // 0..15
    const int c0 = g * CPG;
    const float gm = gamma[c0 + cl] * rstd;
    const float bt = beta[c0 + cl] - mean * gm;

    __shared__ float tile[CPG][257];
    float* tb = t + (long long)b * HW * CH + c0;
    for (int pbase = 0; pbase < HW; pbase += 256) {
#pragma unroll
        for (int c = 0; c < CPG; c++)
            tile[c][tid] = xg[(long long)c * HW + pbase + tid];
        __syncthreads();
#pragma unroll
        for (int pp = 0; pp < 16; pp++) {
            int pl = pp * 16 + pr;
            tb[(long long)(pbase + pl) * CH + cl] = tile[cl][pl] * gm + bt;
        }
        __syncthreads();
    }
}

// ---------------------------------------------------------------------------
// SGEMM-NT: C[m][n] = alpha * sum_k A[m][k]*B[n][k] (+bias[n]) (+resid)
// A: M x K row-major, B: N x K row-major. 128x128x16 tile, 8x8 per thread.
// Double-buffered smem: global loads of tile kt+1 overlap FMAs of tile kt.
// TRANS_OUT: writes C[n][m] (ldm = M), resid indexed [n][m] too.
// All of M,N divisible by 128 and K by 16 in this problem -> no bounds checks.
// ---------------------------------------------------------------------------
template<bool TRANS_OUT, bool ADD_BIAS, bool ADD_RESID>
__global__ void __launch_bounds__(256) sgemm_nt(
    const float* __restrict__ A, const float* __restrict__ Bm,
    float* __restrict__ C, const float* __restrict__ bias,
    const float* __restrict__ resid,
    int M, int N, int K, float alpha,
    long long sA, long long sB, long long sC, long long sR)
{
    __shared__ float As[2][16][132];
    __shared__ float Bs[2][16][132];

    const int z = blockIdx.z;
    A  += z * sA;
    Bm += z * sB;
    C  += z * sC;
    if (ADD_RESID) resid += z * sR;

    const int bm = blockIdx.y * 128;
    const int bn = blockIdx.x * 128;
    const int tid = threadIdx.x;
    const int tr = tid >> 4;      // 0..15
    const int tc = tid & 15;      // 0..15

    // Per-thread load coordinates (2 float4 rows per operand per tile)
    const int r0  = tid >> 2;              // 0..63
    const int r1  = r0 + 64;               // 64..127
    const int col = (tid & 3) << 2;        // 0,4,8,12

    const float* Apl = A  + (long long)(bm + r0) * K + col;
    const float* Aph = A  + (long long)(bm + r1) * K + col;
    const float* Bpl = Bm + (long long)(bn + r0) * K + col;
    const float* Bph = Bm + (long long)(bn + r1) * K + col;

    float acc[8][8];
#pragma unroll
    for (int i = 0; i < 8; i++)
#pragma unroll
        for (int j = 0; j < 8; j++) acc[i][j] = 0.f;

    // prefetch tile 0
    float4 a0 = *(const float4*)(Apl);
    float4 a1 = *(const float4*)(Aph);
    float4 b0 = *(const float4*)(Bpl);
    float4 b1 = *(const float4*)(Bph);

    const int nt = K >> 4;
    int buf = 0;
    // stage tile 0 into smem
    As[0][col+0][r0]=a0.x; As[0][col+1][r0]=a0.y; As[0][col+2][r0]=a0.z; As[0][col+3][r0]=a0.w;
    As[0][col+0][r1]=a1.x; As[0][col+1][r1]=a1.y; As[0][col+2][r1]=a1.z; As[0][col+3][r1]=a1.w;
    Bs[0][col+0][r0]=b0.x; Bs[0][col+1][r0]=b0.y; Bs[0][col+2][r0]=b0.z; Bs[0][col+3][r0]=b0.w;
    Bs[0][col+0][r1]=b1.x; Bs[0][col+1][r1]=b1.y; Bs[0][col+2][r1]=b1.z; Bs[0][col+3][r1]=b1.w;
    __syncthreads();

    for (int kt = 0; kt < nt; kt++) {
        // prefetch next tile from global (overlaps with FMAs below)
        if (kt + 1 < nt) {
            int off = (kt + 1) << 4;
            a0 = *(const float4*)(Apl + off);
            a1 = *(const float4*)(Aph + off);
            b0 = *(const float4*)(Bpl + off);
            b1 = *(const float4*)(Bph + off);
        }
#pragma unroll
        for (int k = 0; k < 16; k++) {
            float a[8], bb[8];
            *(float4*)&a[0]  = *(const float4*)&As[buf][k][tr * 4];
            *(float4*)&a[4]  = *(const float4*)&As[buf][k][tr * 4 + 64];
            *(float4*)&bb[0] = *(const float4*)&Bs[buf][k][tc * 4];
            *(float4*)&bb[4] = *(const float4*)&Bs[buf][k][tc * 4 + 64];
#pragma unroll
            for (int i = 0; i < 8; i++)
#pragma unroll
                for (int j = 0; j < 8; j++)
                    acc[i][j] = fmaf(a[i], bb[j], acc[i][j]);
        }
        if (kt + 1 < nt) {
            int nb = buf ^ 1;
            As[nb][col+0][r0]=a0.x; As[nb][col+1][r0]=a0.y; As[nb][col+2][r0]=a0.z; As[nb][col+3][r0]=a0.w;
            As[nb][col+0][r1]=a1.x; As[nb][col+1][r1]=a1.y; As[nb][col+2][r1]=a1.z; As[nb][col+3][r1]=a1.w;
            Bs[nb][col+0][r0]=b0.x; Bs[nb][col+1][r0]=b0.y; Bs[nb][col+2][r0]=b0.z; Bs[nb][col+3][r0]=b0.w;
            Bs[nb][col+0][r1]=b1.x; Bs[nb][col+1][r1]=b1.y; Bs[nb][col+2][r1]=b1.z; Bs[nb][col+3][r1]=b1.w;
            __syncthreads();
            buf = nb;
        }
    }

    if (!TRANS_OUT) {
#pragma unroll
        for (int i = 0; i < 8; i++) {
            int m = bm + tr * 4 + (i >> 2) * 64 + (i & 3);
#pragma unroll
            for (int jg = 0; jg < 2; jg++) {
                int n0 = bn + tc * 4 + jg * 64;
                float4 v;
                v.x = acc[i][jg*4+0] * alpha; v.y = acc[i][jg*4+1] * alpha;
                v.z = acc[i][jg*4+2] * alpha; v.w = acc[i][jg*4+3] * alpha;
                if (ADD_BIAS) {
                    float4 bv = *(const float4*)(bias + n0);
                    v.x += bv.x; v.y += bv.y; v.z += bv.z; v.w += bv.w;
                }
                if (ADD_RESID) {
                    float4 rv = *(const float4*)(resid + (long long)m * N + n0);
                    v.x += rv.x; v.y += rv.y; v.z += rv.z; v.w += rv.w;
                }
                *(float4*)(C + (long long)m * N + n0) = v;
            }
        }
    } else {
#pragma unroll
        for (int j = 0; j < 8; j++) {
            int n = bn + tc * 4 + (j >> 2) * 64 + (j & 3);
            float bval = ADD_BIAS ? bias[n] : 0.f;
#pragma unroll
            for (int ig = 0; ig < 2; ig++) {
                int m0 = bm + tr * 4 + ig * 64;
                float4 v;
                v.x = acc[ig*4+0][j] * alpha + bval;
                v.y = acc[ig*4+1][j] * alpha + bval;
                v.z = acc[ig*4+2][j] * alpha + bval;
                v.w = acc[ig*4+3][j] * alpha + bval;
                if (ADD_RESID) {
                    float4 rv = *(const float4*)(resid + (long long)n * M + m0);
                    v.x += rv.x; v.y += rv.y; v.z += rv.z; v.w += rv.w;
                }
                *(float4*)(C + (long long)n * M + m0) = v;
            }
        }
    }
}

// ---------------------------------------------------------------------------
// Row softmax over 4096 entries. One block (256 thr) per row; the whole row
// lives in 16 registers/thread between the max and sum passes (no re-read).
// ---------------------------------------------------------------------------
__global__ void __launch_bounds__(256) softmax_kernel(float* __restrict__ s)
{
    float4* row = (float4*)(s + (long long)blockIdx.x * HW);
    const int tid = threadIdx.x;
    const int lane = tid & 31, wid = tid >> 5;
    __shared__ float sh[8];
    __shared__ float s_bcast;

    float4 v[4];
    float m = -INFINITY;
#pragma unroll
    for (int u = 0; u < 4; u++) {
        v[u] = row[tid + u * 256];
        m = fmaxf(m, fmaxf(fmaxf(v[u].x, v[u].y), fmaxf(v[u].z, v[u].w)));
    }
    m = warpMax(m);
    if (lane == 0) sh[wid] = m;
    __syncthreads();
    if (tid < 32) {
        float a = (lane < 8) ? sh[lane] : -INFINITY;
        a = warpMax(a);
        if (lane == 0) s_bcast = a;
    }
    __syncthreads();
    m = s_bcast;

    float sum = 0.f;
#pragma unroll
    for (int u = 0; u < 4; u++) {
        v[u].x = __expf(v[u].x - m); v[u].y = __expf(v[u].y - m);
        v[u].z = __expf(v[u].z - m); v[u].w = __expf(v[u].w - m);
        sum += v[u].x + v[u].y + v[u].z + v[u].w;
    }
    sum = warpSum(sum);
    __syncthreads();
    if (lane == 0) sh[wid] = sum;
    __syncthreads();
    if (tid < 32) {
        float a = (lane < 8) ? sh[lane] : 0.f;
        a = warpSum(a);
        if (lane == 0) s_bcast = a;
    }
    __syncthreads();
    const float inv = 1.f / s_bcast;
#pragma unroll
    for (int u = 0; u < 4; u++) {
        v[u].x *= inv; v[u].y *= inv; v[u].z *= inv; v[u].w *= inv;
        row[tid + u * 256] = v[u];
    }
}

// ---------------------------------------------------------------------------
// Launch
// ---------------------------------------------------------------------------
extern "C" void kernel_launch(void* const* d_in, const int* in_sizes, int n_in,
                              void* d_out, int out_size)
{
    const float* x    = (const float*)d_in[0];
    const float* gn_w = (const float*)d_in[1];
    const float* gn_b = (const float*)d_in[2];
    const float* wq   = (const float*)d_in[3];
    const float* bq   = (const float*)d_in[4];
    const float* wk   = (const float*)d_in[5];
    const float* bk   = (const float*)d_in[6];
    const float* wv   = (const float*)d_in[7];
    const float* bv   = (const float*)d_in[8];
    const float* wo   = (const float*)d_in[9];
    const float* bo   = (const float*)d_in[10];
    float* out = (float*)d_out;

    float *t, *q, *k, *vt, *s;
    cudaGetSymbolAddress((void**)&t,  g_t);
    cudaGetSymbolAddress((void**)&q,  g_q);
    cudaGetSymbolAddress((void**)&k,  g_k);
    cudaGetSymbolAddress((void**)&vt, g_vt);
    cudaGetSymbolAddress((void**)&s,  g_s);
    float* o = t;   // tokens are dead after the V projection; reuse buffer

    const long long sTok = (long long)HW * CH;        // 4096*512
    const long long sSc  = (long long)HW * HW;        // 4096*4096

    // 1) GroupNorm -> tokens (B,HW,C)
    groupnorm_kernel<<<BATCH * GROUPS, 256>>>(x, gn_w, gn_b, t);

    // 2) Q,K projections (normal out), V projection (transposed out)
    dim3 gProj(CH / 128, HW / 128, BATCH);   // (4,32,8)
    sgemm_nt<false, true, false><<<gProj, 256>>>(t, wq, q, bq, nullptr,
        HW, CH, CH, 1.f, sTok, 0, sTok, 0);
    sgemm_nt<false, true, false><<<gProj, 256>>>(t, wk, k, bk, nullptr,
        HW, CH, CH, 1.f, sTok, 0, sTok, 0);
    sgemm_nt<true, true, false><<<gProj, 256>>>(t, wv, vt, bv, nullptr,
        HW, CH, CH, 1.f, sTok, 0, sTok, 0);

    // 3) scores = scale * Q K^T   (B, HW, HW)
    dim3 gSc(HW / 128, HW / 128, BATCH);     // (32,32,8)
    sgemm_nt<false, false, false><<<gSc, 256>>>(q, k, s, nullptr, nullptr,
        HW, HW, CH, SCALE, sTok, sTok, sSc, 0);

    // 4) softmax rows
    softmax_kernel<<<BATCH * HW, 256>>>(s);

    // 5) O = P @ V  (vt is N=C rows x K=HW -> NT again; O overwrites tokens)
    dim3 gPV(CH / 128, HW / 128, BATCH);
    sgemm_nt<false, false, false><<<gPV, 256>>>(s, vt, o, nullptr, nullptr,
        HW, CH, HW, 1.f, sSc, sTok, sTok, 0);

    // 6) out = x + O @ Wo^T + bo, written (B,C,H,W) via transposed epilogue
    sgemm_nt<true, true, true><<<gPV, 256>>>(o, wo, out, bo, x,
        HW, CH, CH, 1.f, sTok, 0, sTok, sTok);
}

// round 5
// speedup vs baseline: 2.7070x; 2.7070x over previous
#include <cuda_runtime.h>
#include <math.h>
#include <stdint.h>

// Problem constants
#define BATCH 8
#define CH    512
#define HW    4096
#define GROUPS 32
#define CPG   16
#define EPS   1e-5f
#define SCALE 0.04419417382415922f   // 512^-0.5

// ---------------------------------------------------------------------------
// Scratch (device globals; allocation in kernel_launch is forbidden)
// ---------------------------------------------------------------------------
__device__ float g_t [(long long)BATCH * HW * CH];   // tokens, later attn out
__device__ float g_q [(long long)BATCH * HW * CH];
__device__ float g_k [(long long)BATCH * HW * CH];
__device__ float g_vt[(long long)BATCH * CH * HW];   // V^T (B,C,HW)
__device__ float g_s [(long long)BATCH * HW * HW];   // scores ~537MB

// ---------------------------------------------------------------------------
__device__ __forceinline__ float warpSum(float v) {
#pragma unroll
    for (int o = 16; o > 0; o >>= 1) v += __shfl_xor_sync(0xffffffffu, v, o);
    return v;
}
__device__ __forceinline__ float warpMax(float v) {
#pragma unroll
    for (int o = 16; o > 0; o >>= 1) v = fmaxf(v, __shfl_xor_sync(0xffffffffu, v, o));
    return v;
}
__device__ __forceinline__ uint32_t f2tf(float x) {
    uint32_t r;
    asm("cvt.rna.tf32.f32 %0, %1;" : "=r"(r) : "f"(x));
    return r;
}
__device__ __forceinline__ void mma8(float* c, const uint32_t* a, const uint32_t* b) {
    asm volatile(
        "mma.sync.aligned.m16n8k8.row.col.f32.tf32.tf32.f32 "
        "{%0,%1,%2,%3},{%4,%5,%6,%7},{%8,%9},{%0,%1,%2,%3};\n"
        : "+f"(c[0]), "+f"(c[1]), "+f"(c[2]), "+f"(c[3])
        : "r"(a[0]), "r"(a[1]), "r"(a[2]), "r"(a[3]), "r"(b[0]), "r"(b[1]));
}

// ---------------------------------------------------------------------------
// GroupNorm + transpose to token-major (B,HW,C)
// ---------------------------------------------------------------------------
__global__ void __launch_bounds__(256) groupnorm_kernel(
    const float* __restrict__ x, const float* __restrict__ gamma,
    const float* __restrict__ beta, float* __restrict__ t)
{
    const int bg = blockIdx.x;
    const int b = bg >> 5, g = bg & 31;
    const int tid = threadIdx.x;
    const float* xg = x + ((long long)b * CH + (long long)g * CPG) * HW;

    float s = 0.f, ss = 0.f;
    const float4* x4 = (const float4*)xg;
    const int n4 = CPG * HW / 4;
    for (int i = tid; i < n4; i += 256) {
        float4 v = x4[i];
        s  += v.x + v.y + v.z + v.w;
        ss += v.x*v.x + v.y*v.y + v.z*v.z + v.w*v.w;
    }
    s = warpSum(s); ss = warpSum(ss);
    __shared__ float shs[8], shss[8];
    __shared__ float s_mean, s_rstd;
    const int lane = tid & 31, wid = tid >> 5;
    if (lane == 0) { shs[wid] = s; shss[wid] = ss; }
    __syncthreads();
    if (tid < 32) {
        float a = (lane < 8) ? shs[lane]  : 0.f;
        float c = (lane < 8) ? shss[lane] : 0.f;
        a = warpSum(a); c = warpSum(c);
        if (lane == 0) {
            const float inv_n = 1.f / (float)(CPG * HW);
            float mean = a * inv_n;
            float var  = c * inv_n - mean * mean;
            s_mean = mean;
            s_rstd = rsqrtf(var + EPS);
        }
    }
    __syncthreads();
    const float mean = s_mean, rstd = s_rstd;

    const int cl = tid & 15;
    const int pr = tid >> 4;
    const int c0 = g * CPG;
    const float gm = gamma[c0 + cl] * rstd;
    const float bt = beta[c0 + cl] - mean * gm;

    __shared__ float tile[CPG][257];
    float* tb = t + (long long)b * HW * CH + c0;
    for (int pbase = 0; pbase < HW; pbase += 256) {
#pragma unroll
        for (int c = 0; c < CPG; c++)
            tile[c][tid] = xg[(long long)c * HW + pbase + tid];
        __syncthreads();
#pragma unroll
        for (int pp = 0; pp < 16; pp++) {
            int pl = pp * 16 + pr;
            tb[(long long)(pbase + pl) * CH + cl] = tile[cl][pl] * gm + bt;
        }
        __syncthreads();
    }
}

// ---------------------------------------------------------------------------
// TF32 tensor-core GEMM-NT: C[m][n] = alpha*sum_k A[m][k]*B[n][k] (+bias)(+resid)
// A: MxK row-major, B: NxK row-major, C: MxN row-major.
// 128x128 block tile, K-tile 16, 8 warps (2x4), warp tile 64x32,
// mma.sync.m16n8k8.tf32. Smem stride 20 => conflict-free fragment reads.
// BIAS: 0 none, 1 per-col (bias[n]), 2 per-row (bias[m]).
// All dims divide tiles exactly in this problem -> no bounds checks.
// ---------------------------------------------------------------------------
template<int BIAS, bool ADD_RESID>
__global__ void __launch_bounds__(256) mma_nt(
    const float* __restrict__ A, const float* __restrict__ Bm,
    float* __restrict__ C, const float* __restrict__ bias,
    const float* __restrict__ resid,
    int M, int N, int K, float alpha,
    long long sA, long long sB, long long sC, long long sR)
{
    __shared__ uint32_t As[2][128][20];
    __shared__ uint32_t Bs[2][128][20];

    const int z = blockIdx.z;
    A  += z * sA;
    Bm += z * sB;
    C  += z * sC;
    if (ADD_RESID) resid += z * sR;

    const int bm = blockIdx.y * 128;
    const int bn = blockIdx.x * 128;
    const int tid  = threadIdx.x;
    const int lane = tid & 31;
    const int wid  = tid >> 5;
    const int wm = wid >> 2;          // 0..1
    const int wn = wid & 3;           // 0..3
    const int g  = lane >> 2;         // 0..7
    const int t  = lane & 3;          // 0..3

    // global load coords: 2 float4 rows per operand per thread
    const int r0  = tid >> 2;         // 0..63
    const int r1  = r0 + 64;
    const int col = (tid & 3) << 2;   // 0,4,8,12

    const float* Apl = A  + (long long)(bm + r0) * K + col;
    const float* Aph = A  + (long long)(bm + r1) * K + col;
    const float* Bpl = Bm + (long long)(bn + r0) * K + col;
    const float* Bph = Bm + (long long)(bn + r1) * K + col;

    float acc[4][4][4];
#pragma unroll
    for (int i = 0; i < 4; i++)
#pragma unroll
        for (int j = 0; j < 4; j++)
#pragma unroll
            for (int e = 0; e < 4; e++) acc[i][j][e] = 0.f;

    float4 a0 = *(const float4*)(Apl);
    float4 a1 = *(const float4*)(Aph);
    float4 b0 = *(const float4*)(Bpl);
    float4 b1 = *(const float4*)(Bph);

    const int nt = K >> 4;
    int buf = 0;

    {   // stage tile 0 (tf32-rounded)
        uint4 u;
        u.x=f2tf(a0.x); u.y=f2tf(a0.y); u.z=f2tf(a0.z); u.w=f2tf(a0.w);
        *(uint4*)&As[0][r0][col] = u;
        u.x=f2tf(a1.x); u.y=f2tf(a1.y); u.z=f2tf(a1.z); u.w=f2tf(a1.w);
        *(uint4*)&As[0][r1][col] = u;
        u.x=f2tf(b0.x); u.y=f2tf(b0.y); u.z=f2tf(b0.z); u.w=f2tf(b0.w);
        *(uint4*)&Bs[0][r0][col] = u;
        u.x=f2tf(b1.x); u.y=f2tf(b1.y); u.z=f2tf(b1.z); u.w=f2tf(b1.w);
        *(uint4*)&Bs[0][r1][col] = u;
    }
    __syncthreads();

    for (int kt = 0; kt < nt; kt++) {
        if (kt + 1 < nt) {
            int off = (kt + 1) << 4;
            a0 = *(const float4*)(Apl + off);
            a1 = *(const float4*)(Aph + off);
            b0 = *(const float4*)(Bpl + off);
            b1 = *(const float4*)(Bph + off);
        }
#pragma unroll
        for (int ks = 0; ks < 2; ks++) {
            const int kk = ks * 8;
            uint32_t af[4][4], bf[4][2];
#pragma unroll
            for (int mt = 0; mt < 4; mt++) {
                const uint32_t* p = &As[buf][wm*64 + mt*16 + g][kk + t];
                af[mt][0] = p[0];
                af[mt][1] = p[8 * 20];
                af[mt][2] = p[4];
                af[mt][3] = p[8 * 20 + 4];
            }
#pragma unroll
            for (int jt = 0; jt < 4; jt++) {
                const uint32_t* p = &Bs[buf][wn*32 + jt*8 + g][kk + t];
                bf[jt][0] = p[0];
                bf[jt][1] = p[4];
            }
#pragma unroll
            for (int mt = 0; mt < 4; mt++)
#pragma unroll
                for (int jt = 0; jt < 4; jt++)
                    mma8(acc[mt][jt], af[mt], bf[jt]);
        }
        if (kt + 1 < nt) {
            int nb = buf ^ 1;
            uint4 u;
            u.x=f2tf(a0.x); u.y=f2tf(a0.y); u.z=f2tf(a0.z); u.w=f2tf(a0.w);
            *(uint4*)&As[nb][r0][col] = u;
            u.x=f2tf(a1.x); u.y=f2tf(a1.y); u.z=f2tf(a1.z); u.w=f2tf(a1.w);
            *(uint4*)&As[nb][r1][col] = u;
            u.x=f2tf(b0.x); u.y=f2tf(b0.y); u.z=f2tf(b0.z); u.w=f2tf(b0.w);
            *(uint4*)&Bs[nb][r0][col] = u;
            u.x=f2tf(b1.x); u.y=f2tf(b1.y); u.z=f2tf(b1.z); u.w=f2tf(b1.w);
            *(uint4*)&Bs[nb][r1][col] = u;
            __syncthreads();
            buf = nb;
        }
    }

    // Epilogue: float2 stores, coalesced row-major
#pragma unroll
    for (int mt = 0; mt < 4; mt++) {
        const int m0 = bm + wm*64 + mt*16 + g;
        const int m1 = m0 + 8;
        float rb0 = 0.f, rb1 = 0.f;
        if (BIAS == 2) { rb0 = bias[m0]; rb1 = bias[m1]; }
#pragma unroll
        for (int jt = 0; jt < 4; jt++) {
            const int n0 = bn + wn*32 + jt*8 + t*2;
            float2 cb = make_float2(0.f, 0.f);
            if (BIAS == 1) cb = *(const float2*)(bias + n0);
            float2 v0, v1;
            v0.x = acc[mt][jt][0]*alpha; v0.y = acc[mt][jt][1]*alpha;
            v1.x = acc[mt][jt][2]*alpha; v1.y = acc[mt][jt][3]*alpha;
            if (BIAS == 1) { v0.x+=cb.x; v0.y+=cb.y; v1.x+=cb.x; v1.y+=cb.y; }
            if (BIAS == 2) { v0.x+=rb0; v0.y+=rb0; v1.x+=rb1; v1.y+=rb1; }
            if (ADD_RESID) {
                float2 r0v = *(const float2*)(resid + (long long)m0 * N + n0);
                float2 r1v = *(const float2*)(resid + (long long)m1 * N + n0);
                v0.x+=r0v.x; v0.y+=r0v.y; v1.x+=r1v.x; v1.y+=r1v.y;
            }
            *(float2*)(C + (long long)m0 * N + n0) = v0;
            *(float2*)(C + (long long)m1 * N + n0) = v1;
        }
    }
}

// ---------------------------------------------------------------------------
// Row softmax over 4096 entries; row lives in registers between passes.
// ---------------------------------------------------------------------------
__global__ void __launch_bounds__(256) softmax_kernel(float* __restrict__ s)
{
    float4* row = (float4*)(s + (long long)blockIdx.x * HW);
    const int tid = threadIdx.x;
    const int lane = tid & 31, wid = tid >> 5;
    __shared__ float sh[8];
    __shared__ float s_bcast;

    float4 v[4];
    float m = -INFINITY;
#pragma unroll
    for (int u = 0; u < 4; u++) {
        v[u] = row[tid + u * 256];
        m = fmaxf(m, fmaxf(fmaxf(v[u].x, v[u].y), fmaxf(v[u].z, v[u].w)));
    }
    m = warpMax(m);
    if (lane == 0) sh[wid] = m;
    __syncthreads();
    if (tid < 32) {
        float a = (lane < 8) ? sh[lane] : -INFINITY;
        a = warpMax(a);
        if (lane == 0) s_bcast = a;
    }
    __syncthreads();
    m = s_bcast;

    float sum = 0.f;
#pragma unroll
    for (int u = 0; u < 4; u++) {
        v[u].x = __expf(v[u].x - m); v[u].y = __expf(v[u].y - m);
        v[u].z = __expf(v[u].z - m); v[u].w = __expf(v[u].w - m);
        sum += v[u].x + v[u].y + v[u].z + v[u].w;
    }
    sum = warpSum(sum);
    __syncthreads();
    if (lane == 0) sh[wid] = sum;
    __syncthreads();
    if (tid < 32) {
        float a = (lane < 8) ? sh[lane] : 0.f;
        a = warpSum(a);
        if (lane == 0) s_bcast = a;
    }
    __syncthreads();
    const float inv = 1.f / s_bcast;
#pragma unroll
    for (int u = 0; u < 4; u++) {
        v[u].x *= inv; v[u].y *= inv; v[u].z *= inv; v[u].w *= inv;
        row[tid + u * 256] = v[u];
    }
}

// ---------------------------------------------------------------------------
// Launch. All GEMMs are NT on tensor cores; transposed outputs realized by
// operand swap (compute W * X^T) instead of scattered epilogues.
// ---------------------------------------------------------------------------
extern "C" void kernel_launch(void* const* d_in, const int* in_sizes, int n_in,
                              void* d_out, int out_size)
{
    const float* x    = (const float*)d_in[0];
    const float* gn_w = (const float*)d_in[1];
    const float* gn_b = (const float*)d_in[2];
    const float* wq   = (const float*)d_in[3];
    const float* bq   = (const float*)d_in[4];
    const float* wk   = (const float*)d_in[5];
    const float* bk   = (const float*)d_in[6];
    const float* wv   = (const float*)d_in[7];
    const float* bv   = (const float*)d_in[8];
    const float* wo   = (const float*)d_in[9];
    const float* bo   = (const float*)d_in[10];
    float* out = (float*)d_out;

    float *t, *q, *k, *vt, *s;
    cudaGetSymbolAddress((void**)&t,  g_t);
    cudaGetSymbolAddress((void**)&q,  g_q);
    cudaGetSymbolAddress((void**)&k,  g_k);
    cudaGetSymbolAddress((void**)&vt, g_vt);
    cudaGetSymbolAddress((void**)&s,  g_s);
    float* o = t;   // tokens dead after V projection; reuse

    const long long sTok = (long long)HW * CH;
    const long long sSc  = (long long)HW * HW;

    // 1) GroupNorm -> tokens (B,HW,C)
    groupnorm_kernel<<<BATCH * GROUPS, 256>>>(x, gn_w, gn_b, t);

    // 2) Q = t @ Wq^T + bq ; K likewise.  M=HW, N=CH, K=CH, col bias.
    dim3 gQK(CH / 128, HW / 128, BATCH);
    mma_nt<1, false><<<gQK, 256>>>(t, wq, q, bq, nullptr,
        HW, CH, CH, 1.f, sTok, 0, sTok, 0);
    mma_nt<1, false><<<gQK, 256>>>(t, wk, k, bk, nullptr,
        HW, CH, CH, 1.f, sTok, 0, sTok, 0);

    // 3) V^T = Wv @ t^T + bv (per-row bias). M=CH, N=HW, K=CH.
    dim3 gVT(HW / 128, CH / 128, BATCH);
    mma_nt<2, false><<<gVT, 256>>>(wv, t, vt, bv, nullptr,
        CH, HW, CH, 1.f, 0, sTok, sTok, 0);

    // 4) scores = scale * Q @ K^T. M=N=HW, K=CH.
    dim3 gSc(HW / 128, HW / 128, BATCH);
    mma_nt<0, false><<<gSc, 256>>>(q, k, s, nullptr, nullptr,
        HW, HW, CH, SCALE, sTok, sTok, sSc, 0);

    // 5) softmax rows
    softmax_kernel<<<BATCH * HW, 256>>>(s);

    // 6) O = P @ V  (B = vt rows are channels: NT). M=HW, N=CH, K=HW.
    dim3 gPV(CH / 128, HW / 128, BATCH);
    mma_nt<0, false><<<gPV, 256>>>(s, vt, o, nullptr, nullptr,
        HW, CH, HW, 1.f, sSc, sTok, sTok, 0);

    // 7) out^T = Wo @ O^T + bo + x, directly in (B,C,HW). M=CH, N=HW, K=CH.
    dim3 gO(HW / 128, CH / 128, BATCH);
    mma_nt<2, true><<<gO, 256>>>(wo, o, out, bo, x,
        CH, HW, CH, 1.f, 0, sTok, sTok, sTok);
}

// round 6
// speedup vs baseline: 2.8670x; 1.0591x over previous
#include <cuda_runtime.h>
#include <math.h>
#include <stdint.h>

// Problem constants
#define BATCH 8
#define CH    512
#define HW    4096
#define GROUPS 32
#define CPG   16
#define EPS   1e-5f
#define SCALE 0.04419417382415922f   // 512^-0.5

// ---------------------------------------------------------------------------
// Scratch (device globals; allocation in kernel_launch is forbidden)
// ---------------------------------------------------------------------------
__device__ float g_t [(long long)BATCH * HW * CH];   // tokens, later attn out
__device__ float g_q [(long long)BATCH * HW * CH];
__device__ float g_k [(long long)BATCH * HW * CH];
__device__ float g_vt[(long long)BATCH * CH * HW];   // V^T (B,C,HW)
__device__ float g_s [(long long)BATCH * HW * HW];   // scores ~537MB

// ---------------------------------------------------------------------------
__device__ __forceinline__ float warpSum(float v) {
#pragma unroll
    for (int o = 16; o > 0; o >>= 1) v += __shfl_xor_sync(0xffffffffu, v, o);
    return v;
}
__device__ __forceinline__ float warpMax(float v) {
#pragma unroll
    for (int o = 16; o > 0; o >>= 1) v = fmaxf(v, __shfl_xor_sync(0xffffffffu, v, o));
    return v;
}
__device__ __forceinline__ void mma8(float* c, const uint32_t* a, const uint32_t* b) {
    asm volatile(
        "mma.sync.aligned.m16n8k8.row.col.f32.tf32.tf32.f32 "
        "{%0,%1,%2,%3},{%4,%5,%6,%7},{%8,%9},{%0,%1,%2,%3};\n"
        : "+f"(c[0]), "+f"(c[1]), "+f"(c[2]), "+f"(c[3])
        : "r"(a[0]), "r"(a[1]), "r"(a[2]), "r"(a[3]), "r"(b[0]), "r"(b[1]));
}
__device__ __forceinline__ void cp16(uint32_t smem_addr, const void* gptr) {
    asm volatile("cp.async.cg.shared.global [%0], [%1], 16;\n"
                 :: "r"(smem_addr), "l"(gptr));
}
__device__ __forceinline__ void cp_commit() {
    asm volatile("cp.async.commit_group;\n" ::: "memory");
}
__device__ __forceinline__ void cp_wait0() {
    asm volatile("cp.async.wait_group 0;\n" ::: "memory");
}

// ---------------------------------------------------------------------------
// GroupNorm + transpose to token-major (B,HW,C)
// ---------------------------------------------------------------------------
__global__ void __launch_bounds__(256) groupnorm_kernel(
    const float* __restrict__ x, const float* __restrict__ gamma,
    const float* __restrict__ beta, float* __restrict__ t)
{
    const int bg = blockIdx.x;
    const int b = bg >> 5, g = bg & 31;
    const int tid = threadIdx.x;
    const float* xg = x + ((long long)b * CH + (long long)g * CPG) * HW;

    float s = 0.f, ss = 0.f;
    const float4* x4 = (const float4*)xg;
    const int n4 = CPG * HW / 4;
    for (int i = tid; i < n4; i += 256) {
        float4 v = x4[i];
        s  += v.x + v.y + v.z + v.w;
        ss += v.x*v.x + v.y*v.y + v.z*v.z + v.w*v.w;
    }
    s = warpSum(s); ss = warpSum(ss);
    __shared__ float shs[8], shss[8];
    __shared__ float s_mean, s_rstd;
    const int lane = tid & 31, wid = tid >> 5;
    if (lane == 0) { shs[wid] = s; shss[wid] = ss; }
    __syncthreads();
    if (tid < 32) {
        float a = (lane < 8) ? shs[lane]  : 0.f;
        float c = (lane < 8) ? shss[lane] : 0.f;
        a = warpSum(a); c = warpSum(c);
        if (lane == 0) {
            const float inv_n = 1.f / (float)(CPG * HW);
            float mean = a * inv_n;
            float var  = c * inv_n - mean * mean;
            s_mean = mean;
            s_rstd = rsqrtf(var + EPS);
        }
    }
    __syncthreads();
    const float mean = s_mean, rstd = s_rstd;

    const int cl = tid & 15;
    const int pr = tid >> 4;
    const int c0 = g * CPG;
    const float gm = gamma[c0 + cl] * rstd;
    const float bt = beta[c0 + cl] - mean * gm;

    __shared__ float tile[CPG][257];
    float* tb = t + (long long)b * HW * CH + c0;
    for (int pbase = 0; pbase < HW; pbase += 256) {
#pragma unroll
        for (int c = 0; c < CPG; c++)
            tile[c][tid] = xg[(long long)c * HW + pbase + tid];
        __syncthreads();
#pragma unroll
        for (int pp = 0; pp < 16; pp++) {
            int pl = pp * 16 + pr;
            tb[(long long)(pbase + pl) * CH + cl] = tile[cl][pl] * gm + bt;
        }
        __syncthreads();
    }
}

// ---------------------------------------------------------------------------
// TF32 tensor-core GEMM-NT: C[m][n] = alpha*sum_k A[m][k]*B[n][k] (+bias)(+resid)
// A: MxK row-major, B: NxK row-major, C: MxN row-major.
// 128x128 block tile, K-tile 16, 8 warps (2x4), warp tile 64x32.
// cp.async staging of raw fp32 (mma.tf32 truncates mantissa in HW — the
// standard CUTLASS sm80 tf32 path; removes CVT+STS register staging).
// 2-stage smem buffer, 1 __syncthreads per K-tile.
// BIAS: 0 none, 1 per-col (bias[n]), 2 per-row (bias[m]).
// All dims divide tiles exactly in this problem -> no bounds checks.
// ---------------------------------------------------------------------------
template<int BIAS, bool ADD_RESID>
__global__ void __launch_bounds__(256, 2) mma_nt(
    const float* __restrict__ A, const float* __restrict__ Bm,
    float* __restrict__ C, const float* __restrict__ bias,
    const float* __restrict__ resid,
    int M, int N, int K, float alpha,
    long long sA, long long sB, long long sC, long long sR)
{
    __shared__ uint32_t As[2][128][20];
    __shared__ uint32_t Bs[2][128][20];

    const int z = blockIdx.z;
    A  += z * sA;
    Bm += z * sB;
    C  += z * sC;
    if (ADD_RESID) resid += z * sR;

    const int bm = blockIdx.y * 128;
    const int bn = blockIdx.x * 128;
    const int tid  = threadIdx.x;
    const int lane = tid & 31;
    const int wid  = tid >> 5;
    const int wm = wid >> 2;          // 0..1
    const int wn = wid & 3;           // 0..3
    const int g  = lane >> 2;         // 0..7
    const int t  = lane & 3;          // 0..3

    // global load coords: 2 16B chunks per operand per thread
    const int r0  = tid >> 2;         // 0..63
    const int r1  = r0 + 64;
    const int col = (tid & 3) << 2;   // 0,4,8,12

    const float* Apl = A  + (long long)(bm + r0) * K + col;
    const float* Aph = A  + (long long)(bm + r1) * K + col;
    const float* Bpl = Bm + (long long)(bn + r0) * K + col;
    const float* Bph = Bm + (long long)(bn + r1) * K + col;

    // smem destinations for the two stages
    uint32_t dA0[2], dA1[2], dB0[2], dB1[2];
#pragma unroll
    for (int b2 = 0; b2 < 2; b2++) {
        dA0[b2] = (uint32_t)__cvta_generic_to_shared(&As[b2][r0][col]);
        dA1[b2] = (uint32_t)__cvta_generic_to_shared(&As[b2][r1][col]);
        dB0[b2] = (uint32_t)__cvta_generic_to_shared(&Bs[b2][r0][col]);
        dB1[b2] = (uint32_t)__cvta_generic_to_shared(&Bs[b2][r1][col]);
    }

    float acc[4][4][4];
#pragma unroll
    for (int i = 0; i < 4; i++)
#pragma unroll
        for (int j = 0; j < 4; j++)
#pragma unroll
            for (int e = 0; e < 4; e++) acc[i][j][e] = 0.f;

    const int nt = K >> 4;

    // prologue: stage 0
    cp16(dA0[0], Apl); cp16(dA1[0], Aph);
    cp16(dB0[0], Bpl); cp16(dB1[0], Bph);
    cp_commit();

    int buf = 0;
    for (int kt = 0; kt < nt; kt++) {
        cp_wait0();
        __syncthreads();          // stage `buf` ready; all warps done with buf^1

        if (kt + 1 < nt) {        // prefetch next tile into buf^1 (overlaps MMAs)
            int off = (kt + 1) << 4;
            int nb = buf ^ 1;
            cp16(dA0[nb], Apl + off); cp16(dA1[nb], Aph + off);
            cp16(dB0[nb], Bpl + off); cp16(dB1[nb], Bph + off);
            cp_commit();
        }

#pragma unroll
        for (int ks = 0; ks < 2; ks++) {
            const int kk = ks * 8;
            uint32_t af[4][4], bf[4][2];
#pragma unroll
            for (int mt = 0; mt < 4; mt++) {
                const uint32_t* p = &As[buf][wm*64 + mt*16 + g][kk + t];
                af[mt][0] = p[0];
                af[mt][1] = p[8 * 20];
                af[mt][2] = p[4];
                af[mt][3] = p[8 * 20 + 4];
            }
#pragma unroll
            for (int jt = 0; jt < 4; jt++) {
                const uint32_t* p = &Bs[buf][wn*32 + jt*8 + g][kk + t];
                bf[jt][0] = p[0];
                bf[jt][1] = p[4];
            }
#pragma unroll
            for (int mt = 0; mt < 4; mt++)
#pragma unroll
                for (int jt = 0; jt < 4; jt++)
                    mma8(acc[mt][jt], af[mt], bf[jt]);
        }
        buf ^= 1;
    }

    // Epilogue: float2 stores, coalesced row-major
#pragma unroll
    for (int mt = 0; mt < 4; mt++) {
        const int m0 = bm + wm*64 + mt*16 + g;
        const int m1 = m0 + 8;
        float rb0 = 0.f, rb1 = 0.f;
        if (BIAS == 2) { rb0 = bias[m0]; rb1 = bias[m1]; }
#pragma unroll
        for (int jt = 0; jt < 4; jt++) {
            const int n0 = bn + wn*32 + jt*8 + t*2;
            float2 cb = make_float2(0.f, 0.f);
            if (BIAS == 1) cb = *(const float2*)(bias + n0);
            float2 v0, v1;
            v0.x = acc[mt][jt][0]*alpha; v0.y = acc[mt][jt][1]*alpha;
            v1.x = acc[mt][jt][2]*alpha; v1.y = acc[mt][jt][3]*alpha;
            if (BIAS == 1) { v0.x+=cb.x; v0.y+=cb.y; v1.x+=cb.x; v1.y+=cb.y; }
            if (BIAS == 2) { v0.x+=rb0; v0.y+=rb0; v1.x+=rb1; v1.y+=rb1; }
            if (ADD_RESID) {
                float2 r0v = *(const float2*)(resid + (long long)m0 * N + n0);
                float2 r1v = *(const float2*)(resid + (long long)m1 * N + n0);
                v0.x+=r0v.x; v0.y+=r0v.y; v1.x+=r1v.x; v1.y+=r1v.y;
            }
            *(float2*)(C + (long long)m0 * N + n0) = v0;
            *(float2*)(C + (long long)m1 * N + n0) = v1;
        }
    }
}

// ---------------------------------------------------------------------------
// Row softmax over 4096 entries; row lives in registers between passes.
// ---------------------------------------------------------------------------
__global__ void __launch_bounds__(256) softmax_kernel(float* __restrict__ s)
{
    float4* row = (float4*)(s + (long long)blockIdx.x * HW);
    const int tid = threadIdx.x;
    const int lane = tid & 31, wid = tid >> 5;
    __shared__ float sh[8];
    __shared__ float s_bcast;

    float4 v[4];
    float m = -INFINITY;
#pragma unroll
    for (int u = 0; u < 4; u++) {
        v[u] = row[tid + u * 256];
        m = fmaxf(m, fmaxf(fmaxf(v[u].x, v[u].y), fmaxf(v[u].z, v[u].w)));
    }
    m = warpMax(m);
    if (lane == 0) sh[wid] = m;
    __syncthreads();
    if (tid < 32) {
        float a = (lane < 8) ? sh[lane] : -INFINITY;
        a = warpMax(a);
        if (lane == 0) s_bcast = a;
    }
    __syncthreads();
    m = s_bcast;

    float sum = 0.f;
#pragma unroll
    for (int u = 0; u < 4; u++) {
        v[u].x = __expf(v[u].x - m); v[u].y = __expf(v[u].y - m);
        v[u].z = __expf(v[u].z - m); v[u].w = __expf(v[u].w - m);
        sum += v[u].x + v[u].y + v[u].z + v[u].w;
    }
    sum = warpSum(sum);
    __syncthreads();
    if (lane == 0) sh[wid] = sum;
    __syncthreads();
    if (tid < 32) {
        float a = (lane < 8) ? sh[lane] : 0.f;
        a = warpSum(a);
        if (lane == 0) s_bcast = a;
    }
    __syncthreads();
    const float inv = 1.f / s_bcast;
#pragma unroll
    for (int u = 0; u < 4; u++) {
        v[u].x *= inv; v[u].y *= inv; v[u].z *= inv; v[u].w *= inv;
        row[tid + u * 256] = v[u];
    }
}

// ---------------------------------------------------------------------------
// Launch. All GEMMs are NT on tensor cores; transposed outputs realized by
// operand swap (compute W * X^T) instead of scattered epilogues.
// ---------------------------------------------------------------------------
extern "C" void kernel_launch(void* const* d_in, const int* in_sizes, int n_in,
                              void* d_out, int out_size)
{
    const float* x    = (const float*)d_in[0];
    const float* gn_w = (const float*)d_in[1];
    const float* gn_b = (const float*)d_in[2];
    const float* wq   = (const float*)d_in[3];
    const float* bq   = (const float*)d_in[4];
    const float* wk   = (const float*)d_in[5];
    const float* bk   = (const float*)d_in[6];
    const float* wv   = (const float*)d_in[7];
    const float* bv   = (const float*)d_in[8];
    const float* wo   = (const float*)d_in[9];
    const float* bo   = (const float*)d_in[10];
    float* out = (float*)d_out;

    float *t, *q, *k, *vt, *s;
    cudaGetSymbolAddress((void**)&t,  g_t);
    cudaGetSymbolAddress((void**)&q,  g_q);
    cudaGetSymbolAddress((void**)&k,  g_k);
    cudaGetSymbolAddress((void**)&vt, g_vt);
    cudaGetSymbolAddress((void**)&s,  g_s);
    float* o = t;   // tokens dead after V projection; reuse

    const long long sTok = (long long)HW * CH;
    const long long sSc  = (long long)HW * HW;

    // 1) GroupNorm -> tokens (B,HW,C)
    groupnorm_kernel<<<BATCH * GROUPS, 256>>>(x, gn_w, gn_b, t);

    // 2) Q = t @ Wq^T + bq ; K likewise.  M=HW, N=CH, K=CH, col bias.
    dim3 gQK(CH / 128, HW / 128, BATCH);
    mma_nt<1, false><<<gQK, 256>>>(t, wq, q, bq, nullptr,
        HW, CH, CH, 1.f, sTok, 0, sTok, 0);
    mma_nt<1, false><<<gQK, 256>>>(t, wk, k, bk, nullptr,
        HW, CH, CH, 1.f, sTok, 0, sTok, 0);

    // 3) V^T = Wv @ t^T + bv (per-row bias). M=CH, N=HW, K=CH.
    dim3 gVT(HW / 128, CH / 128, BATCH);
    mma_nt<2, false><<<gVT, 256>>>(wv, t, vt, bv, nullptr,
        CH, HW, CH, 1.f, 0, sTok, sTok, 0);

    // 4) scores = scale * Q @ K^T. M=N=HW, K=CH.
    dim3 gSc(HW / 128, HW / 128, BATCH);
    mma_nt<0, false><<<gSc, 256>>>(q, k, s, nullptr, nullptr,
        HW, HW, CH, SCALE, sTok, sTok, sSc, 0);

    // 5) softmax rows
    softmax_kernel<<<BATCH * HW, 256>>>(s);

    // 6) O = P @ V  (B = vt rows are channels: NT). M=HW, N=CH, K=HW.
    dim3 gPV(CH / 128, HW / 128, BATCH);
    mma_nt<0, false><<<gPV, 256>>>(s, vt, o, nullptr, nullptr,
        HW, CH, HW, 1.f, sSc, sTok, sTok, 0);

    // 7) out^T = Wo @ O^T + bo + x, directly in (B,C,HW). M=CH, N=HW, K=CH.
    dim3 gO(HW / 128, CH / 128, BATCH);
    mma_nt<2, true><<<gO, 256>>>(wo, o, out, bo, x,
        CH, HW, CH, 1.f, 0, sTok, sTok, sTok);
}